// round 16
// baseline (speedup 1.0000x reference)
#include <cuda_runtime.h>
#include <cuda_fp16.h>
#include <cstdint>
#include <cstddef>

// ---------------- problem constants ----------------
#define N_X    20000
#define N_GENE 4264
#define NN     24264
#define EE     120000
#define NREL   4
#define NSLOT  (NREL * NN)
#define NBLK   ((NSLOT + 1023) / 1024)

#define IN1    1613
#define OUT1   1600
#define OUT2   900
#define OUT3   400

// segmented fp16 layouts (16B-aligned segments)
#define SEG1   1616      // layer1 segment width (1613 valid + 3 zero)
#define KP1    8096      // 5*1616=8080, padded to mult of 32
#define SEG2   1600
#define KP2    8000      // 5*1600
#define KP3    960       // 900 padded

// ---------------- device scratch ----------------
__device__ __half gA1[(size_t)NN * KP1 + 64];
__device__ __half gA2[(size_t)NN * KP2 + 64];
__device__ __half gA3[(size_t)NN * KP3 + 64];
__device__ __half gBh[(size_t)1600 * KP1 + 64];
__device__ float  gH3[(size_t)NN * OUT3 + 64];
__device__ int    gCntI[NSLOT];
__device__ int    gOff[NSLOT + 1];
__device__ int    gCur[NSLOT];
__device__ int    gBlkSum[NBLK];
__device__ int    gSrcSorted[EE];
__device__ int    g_is64;

// ---------------- edge dtype detect ----------------
__global__ void detect_k(const unsigned int* __restrict__ ei) {
    if (blockIdx.x == 0 && threadIdx.x == 0) {
        int is64 = 1;
        for (int i = 1; i < 256; i += 2)
            if (ei[i] != 0u) { is64 = 0; break; }
        g_is64 = is64;
    }
}
__device__ __forceinline__ int read_idx(const void* p, int i, int is64) {
    return is64 ? (int)((const long long*)p)[i] : ((const int*)p)[i];
}

// ---------------- counting sort of edges by (rel,dst) ----------------
__global__ void zero_i_k(int* __restrict__ p, int n) {
    int i = blockIdx.x * blockDim.x + threadIdx.x;
    if (i < n) p[i] = 0;
}
__global__ void count_i_k(const void* __restrict__ ei, const void* __restrict__ et) {
    int e = blockIdx.x * blockDim.x + threadIdx.x;
    if (e >= EE) return;
    int is64 = g_is64;
    int r   = read_idx(et, e, is64);
    int dst = read_idx(ei, EE + e, is64);
    atomicAdd(&gCntI[r * NN + dst], 1);
}
__global__ void scanA_k() {
    __shared__ int sdata[1024];
    const int tid = threadIdx.x;
    const int i = blockIdx.x * 1024 + tid;
    int v = (i < NSLOT) ? gCntI[i] : 0;
    sdata[tid] = v;
    __syncthreads();
    for (int off = 1; off < 1024; off <<= 1) {
        int t = (tid >= off) ? sdata[tid - off] : 0;
        __syncthreads();
        sdata[tid] += t;
        __syncthreads();
    }
    if (i < NSLOT) gOff[i] = sdata[tid] - v;
    if (tid == 1023) gBlkSum[blockIdx.x] = sdata[1023];
}
__global__ void scanB_k() {
    if (threadIdx.x == 0) {
        int acc = 0;
        for (int b = 0; b < NBLK; b++) {
            int v = gBlkSum[b];
            gBlkSum[b] = acc;
            acc += v;
        }
    }
}
__global__ void scanC_k() {
    int i = blockIdx.x * blockDim.x + threadIdx.x;
    if (i < NSLOT) {
        int v = gOff[i] + gBlkSum[i >> 10];
        gOff[i] = v;
        gCur[i] = v;
    }
    if (i == 0) gOff[NSLOT] = EE;
}
__global__ void fill_k(const void* __restrict__ ei, const void* __restrict__ et) {
    int e = blockIdx.x * blockDim.x + threadIdx.x;
    if (e >= EE) return;
    int is64 = g_is64;
    int src = read_idx(ei, e, is64);
    int dst = read_idx(ei, EE + e, is64);
    int r   = read_idx(et, e, is64);
    int p = atomicAdd(&gCur[r * NN + dst], 1);
    gSrcSorted[p] = src;
}

// ---------------- build h (fp16) ----------------
__global__ void build_h16_k(const float* __restrict__ x, const float* __restrict__ ge) {
    int i = blockIdx.y;
    int k = blockIdx.x * blockDim.x + threadIdx.x;
    if (k >= IN1) return;
    float v = (i < N_X) ? x[(size_t)i * IN1 + k] : ge[(size_t)(i - N_X) * IN1 + k];
    gA1[(size_t)i * KP1 + k] = __float2half(v);
}

// ---------------- vectorized gather aggregation (uint4, atomic-free) ----------------
#define AGG_T 128
__global__ __launch_bounds__(AGG_T) void aggv_k(
    const __half* __restrict__ src, __half* __restrict__ dstA,
    int ld, int segH, int nvec)
{
    const int slot = blockIdx.x;
    const int r    = slot / NN;
    const int drow = slot - r * NN;
    const int beg = gOff[slot];
    const int end = gOff[slot + 1];
    const int tid = threadIdx.x;
    uint4* outv = (uint4*)(dstA + (size_t)drow * ld + (size_t)(r + 1) * segH);

    const int v0 = tid, v1 = tid + AGG_T;
    if (end <= beg) {
        uint4 z = make_uint4(0, 0, 0, 0);
        if (v0 < nvec) outv[v0] = z;
        if (v1 < nvec) outv[v1] = z;
        return;
    }
    const float inv = 1.0f / (float)(end - beg);
    float a0[8], a1[8];
#pragma unroll
    for (int j = 0; j < 8; j++) { a0[j] = 0.f; a1[j] = 0.f; }

    for (int e = beg; e < end; e++) {
        const uint4* s = (const uint4*)(src + (size_t)gSrcSorted[e] * ld);
        if (v0 < nvec) {
            uint4 q = s[v0];
            float2 f0 = __half22float2(*(__half2*)&q.x);
            float2 f1 = __half22float2(*(__half2*)&q.y);
            float2 f2 = __half22float2(*(__half2*)&q.z);
            float2 f3 = __half22float2(*(__half2*)&q.w);
            a0[0] += f0.x; a0[1] += f0.y; a0[2] += f1.x; a0[3] += f1.y;
            a0[4] += f2.x; a0[5] += f2.y; a0[6] += f3.x; a0[7] += f3.y;
        }
        if (v1 < nvec) {
            uint4 q = s[v1];
            float2 f0 = __half22float2(*(__half2*)&q.x);
            float2 f1 = __half22float2(*(__half2*)&q.y);
            float2 f2 = __half22float2(*(__half2*)&q.z);
            float2 f3 = __half22float2(*(__half2*)&q.w);
            a1[0] += f0.x; a1[1] += f0.y; a1[2] += f1.x; a1[3] += f1.y;
            a1[4] += f2.x; a1[5] += f2.y; a1[6] += f3.x; a1[7] += f3.y;
        }
    }
    if (v0 < nvec) {
        uint4 q;
        *(__half2*)&q.x = __floats2half2_rn(a0[0] * inv, a0[1] * inv);
        *(__half2*)&q.y = __floats2half2_rn(a0[2] * inv, a0[3] * inv);
        *(__half2*)&q.z = __floats2half2_rn(a0[4] * inv, a0[5] * inv);
        *(__half2*)&q.w = __floats2half2_rn(a0[6] * inv, a0[7] * inv);
        outv[v0] = q;
    }
    if (v1 < nvec) {
        uint4 q;
        *(__half2*)&q.x = __floats2half2_rn(a1[0] * inv, a1[1] * inv);
        *(__half2*)&q.y = __floats2half2_rn(a1[2] * inv, a1[3] * inv);
        *(__half2*)&q.z = __floats2half2_rn(a1[4] * inv, a1[5] * inv);
        *(__half2*)&q.w = __floats2half2_rn(a1[6] * inv, a1[7] * inv);
        outv[v1] = q;
    }
}

// ---------------- coalesced segmented weight transpose -> fp16 K-major ----------------
__global__ void convwT_k(const float* __restrict__ root, const float* __restrict__ W,
                         int rows1, int segW, int nseg,
                         int Nout, __half* __restrict__ D, int ldd) {
    __shared__ float tile[32][33];
    const int k0 = blockIdx.x * 32;
    const int n0 = blockIdx.y * 32;
    const int tx = threadIdx.x, ty = threadIdx.y;   // 32 x 8
#pragma unroll
    for (int j = 0; j < 32; j += 8) {
        int k = k0 + ty + j;
        int n = n0 + tx;
        float v = 0.f;
        if (n < Nout && k < ldd) {
            int seg = k / segW;
            int idx = k - seg * segW;
            if (seg < nseg && idx < rows1) {
                if (seg == 0) v = root[(size_t)idx * Nout + n];
                else          v = W[(size_t)((seg - 1) * rows1 + idx) * Nout + n];
            }
        }
        tile[ty + j][tx] = v;
    }
    __syncthreads();
#pragma unroll
    for (int j = 0; j < 32; j += 8) {
        int n = n0 + ty + j;
        int k = k0 + tx;
        if (n < Nout && k < ldd)
            D[(size_t)n * ldd + k] = __float2half(tile[tx][ty + j]);
    }
}

// ---------------- mma.sync fp16 GEMM (unchanged known-good core) ----------------
#define GT      256
#define ROW_B   80
#define A_TILE  (256 * ROW_B)
#define B_TILE  (128 * ROW_B)
#define OFF_A   0
#define OFF_B   A_TILE
#define STAGE_B (A_TILE + B_TILE)
#define NSTAGE  4
#define DSMEM   (NSTAGE * STAGE_B)

__device__ __forceinline__ void cp_async16(uint32_t dst, const void* src, bool ok) {
    int sz = ok ? 16 : 0;
    asm volatile("cp.async.cg.shared.global [%0], [%1], 16, %2;"
                 :: "r"(dst), "l"(src), "r"(sz));
}
__device__ __forceinline__ uint32_t smem_u32(const void* p) {
    uint32_t a;
    asm("{ .reg .u64 t; cvta.to.shared.u64 t, %1; cvt.u32.u64 %0, t; }" : "=r"(a) : "l"(p));
    return a;
}
__device__ __forceinline__ void ldsm4(uint32_t* r, uint32_t addr) {
    asm volatile("ldmatrix.sync.aligned.m8n8.x4.shared.b16 {%0,%1,%2,%3}, [%4];"
                 : "=r"(r[0]), "=r"(r[1]), "=r"(r[2]), "=r"(r[3]) : "r"(addr));
}
__device__ __forceinline__ void mma_f16(float* d, const uint32_t* a, uint32_t b0, uint32_t b1) {
    asm volatile("mma.sync.aligned.m16n8k16.row.col.f32.f16.f16.f32 "
                 "{%0,%1,%2,%3}, {%4,%5,%6,%7}, {%8,%9}, {%0,%1,%2,%3};"
                 : "+f"(d[0]), "+f"(d[1]), "+f"(d[2]), "+f"(d[3])
                 : "r"(a[0]), "r"(a[1]), "r"(a[2]), "r"(a[3]), "r"(b0), "r"(b1));
}

__global__ __launch_bounds__(GT, 1) void hgemm_k(
    const __half* __restrict__ Ah, const __half* __restrict__ Bh,
    const float* __restrict__ bias,
    float* __restrict__ C32, int ldc32,
    __half* __restrict__ C16, int ldc16,
    int M, int Ncols, int Kpad, int doRelu)
{
    extern __shared__ char dsm[];
    const uint32_t dsmU = smem_u32(dsm);

    const int tid  = threadIdx.x;
    const int wid  = tid >> 5;
    const int lane = tid & 31;
    const int warp_m = wid & 3;
    const int warp_n = wid >> 2;
    const int mbase = blockIdx.y * 256;
    const int nbase = blockIdx.x * 128;
    const int nChunks = Kpad >> 5;

    float cf[4][8][4];
#pragma unroll
    for (int mi = 0; mi < 4; mi++)
#pragma unroll
        for (int nb = 0; nb < 8; nb++)
#pragma unroll
            for (int r = 0; r < 4; r++) cf[mi][nb][r] = 0.f;

    const bool mOK = (mbase + tid) < M;
    const int  bRow = tid >> 1;
    const int  bHalf = tid & 1;
    const bool nOK = (nbase + bRow) < Ncols;
    const __half* pA = Ah + (size_t)(mbase + tid) * Kpad;
    const __half* pB = Bh + (size_t)(nbase + bRow) * Kpad + bHalf * 16;
    const uint32_t dstA = OFF_A + tid * ROW_B;
    const uint32_t dstB = OFF_B + bRow * ROW_B + bHalf * 32;

    auto issue = [&](int i) {
        const int s = i & 3;
        const int k0 = i << 5;
        const uint32_t st = dsmU + s * STAGE_B;
#pragma unroll
        for (int c = 0; c < 4; c++)
            cp_async16(st + dstA + c * 16, pA + k0 + c * 8, mOK);
#pragma unroll
        for (int c = 0; c < 2; c++)
            cp_async16(st + dstB + c * 16, pB + k0 + c * 8, nOK);
        asm volatile("cp.async.commit_group;" ::: "memory");
    };

    issue(0);
    if (nChunks > 1) issue(1);
    if (nChunks > 2) issue(2);

    const int lrow  = lane & 15;
    const int lhalf = (lane >> 4) << 4;
    const uint32_t aOff = OFF_A + (warp_m * 64 + lrow) * ROW_B + lhalf;
    const uint32_t bOff = OFF_B + (warp_n * 64 + lrow) * ROW_B + lhalf;

    for (int i = 0; i < nChunks; i++) {
        const int rem = nChunks - 1 - i;
        if (rem >= 2)      asm volatile("cp.async.wait_group 2;" ::: "memory");
        else if (rem == 1) asm volatile("cp.async.wait_group 1;" ::: "memory");
        else               asm volatile("cp.async.wait_group 0;" ::: "memory");
        __syncthreads();
        if (i + 3 < nChunks) issue(i + 3);

        const uint32_t st = dsmU + (i & 3) * STAGE_B;
        const uint32_t aA = st + aOff;
        const uint32_t bA = st + bOff;

#pragma unroll
        for (int kk = 0; kk < 2; kk++) {
            const uint32_t kByte = kk << 5;
            uint32_t aQ[4][4], bQ[4][4];
#pragma unroll
            for (int mi = 0; mi < 4; mi++)
                ldsm4(aQ[mi], aA + mi * (16 * ROW_B) + kByte);
#pragma unroll
            for (int nj = 0; nj < 4; nj++)
                ldsm4(bQ[nj], bA + nj * (16 * ROW_B) + kByte);
#pragma unroll
            for (int mi = 0; mi < 4; mi++)
#pragma unroll
                for (int nj = 0; nj < 4; nj++) {
                    mma_f16(cf[mi][nj * 2 + 0], aQ[mi], bQ[nj][0], bQ[nj][2]);
                    mma_f16(cf[mi][nj * 2 + 1], aQ[mi], bQ[nj][1], bQ[nj][3]);
                }
        }
    }

    const int r0 = mbase + warp_m * 64 + (lane >> 2);
    const int c0 = nbase + warp_n * 64 + ((lane & 3) << 1);
#pragma unroll
    for (int nb = 0; nb < 8; nb++) {
        const int gc = c0 + nb * 8;
        if (gc >= Ncols) continue;
        const float bv0 = bias[gc], bv1 = bias[gc + 1];
#pragma unroll
        for (int mi = 0; mi < 4; mi++) {
            int gr = r0 + mi * 16;
            float v0 = cf[mi][nb][0] + bv0, v1 = cf[mi][nb][1] + bv1;
            float v2 = cf[mi][nb][2] + bv0, v3 = cf[mi][nb][3] + bv1;
            if (doRelu) {
                v0 = fmaxf(v0, 0.f); v1 = fmaxf(v1, 0.f);
                v2 = fmaxf(v2, 0.f); v3 = fmaxf(v3, 0.f);
            }
            if (C32) {
                if (gr < M)     *(float2*)(C32 + (size_t)gr * ldc32 + gc)       = make_float2(v0, v1);
                if (gr + 8 < M) *(float2*)(C32 + (size_t)(gr + 8) * ldc32 + gc) = make_float2(v2, v3);
            }
            if (C16) {
                if (gr < M)     *(__half2*)(C16 + (size_t)gr * ldc16 + gc)       = __floats2half2_rn(v0, v1);
                if (gr + 8 < M) *(__half2*)(C16 + (size_t)(gr + 8) * ldc16 + gc) = __floats2half2_rn(v2, v3);
            }
        }
    }
}

// ---------------- final head ----------------
__global__ void head_k(const float* __restrict__ lin2, const float* __restrict__ b,
                       float* __restrict__ out) {
    int row  = blockIdx.x * (blockDim.x >> 5) + (threadIdx.x >> 5);
    int lane = threadIdx.x & 31;
    if (row >= NN) return;
    const float* h = gH3 + (size_t)row * OUT3;
    float a0 = 0.f, a1 = 0.f;
    for (int k = lane; k < OUT3; k += 32) {
        float v = h[k];
        a0 += v * lin2[k * 2 + 0];
        a1 += v * lin2[k * 2 + 1];
    }
#pragma unroll
    for (int o = 16; o; o >>= 1) {
        a0 += __shfl_down_sync(0xffffffffu, a0, o);
        a1 += __shfl_down_sync(0xffffffffu, a1, o);
    }
    if (lane == 0) {
        a0 += b[0]; a1 += b[1];
        float m = fmaxf(a0, a1);
        float lse = m + logf(expf(a0 - m) + expf(a1 - m));
        out[row * 2 + 0] = a0 - lse;
        out[row * 2 + 1] = a1 - lse;
    }
}

// ---------------- host ----------------
static float* sym_addr_f(const void* s) { void* p = nullptr; cudaGetSymbolAddress(&p, s); return (float*)p; }
static __half* sym_addr_h(const void* s) { void* p = nullptr; cudaGetSymbolAddress(&p, s); return (__half*)p; }
static int* sym_addr_i(const void* s) { void* p = nullptr; cudaGetSymbolAddress(&p, s); return (int*)p; }

extern "C" void kernel_launch(void* const* d_in, const int* in_sizes, int n_in,
                              void* d_out, int out_size) {
    const float* x        = (const float*)d_in[0];
    const void*  eidx     = d_in[1];
    const void*  etype    = d_in[2];
    const float* gene_emb = (const float*)d_in[3];
    const float* W1       = (const float*)d_in[4];
    const float* root1    = (const float*)d_in[5];
    const float* b1       = (const float*)d_in[6];
    const float* W2       = (const float*)d_in[7];
    const float* root2    = (const float*)d_in[8];
    const float* b2       = (const float*)d_in[9];
    const float* lin1_w   = (const float*)d_in[10];
    const float* lin1_b   = (const float*)d_in[11];
    const float* lin2_w   = (const float*)d_in[12];
    const float* lin2_b   = (const float*)d_in[13];
    float* out = (float*)d_out;

    __half* A1 = sym_addr_h(gA1);
    __half* A2 = sym_addr_h(gA2);
    __half* A3 = sym_addr_h(gA3);
    __half* Bh = sym_addr_h(gBh);
    float*  H3 = sym_addr_f(gH3);
    int*    CntI = sym_addr_i(gCntI);

    static bool attr_done = false;
    if (!attr_done) {
        cudaFuncSetAttribute(hgemm_k, cudaFuncAttributeMaxDynamicSharedMemorySize, DSMEM);
        attr_done = true;
    }

    // ---- edge preprocessing: dtype, counting sort by (rel,dst) ----
    detect_k<<<1, 1>>>((const unsigned int*)eidx);
    zero_i_k<<<(NSLOT + 255) / 256, 256>>>(CntI, NSLOT);
    count_i_k<<<(EE + 255) / 256, 256>>>(eidx, etype);
    scanA_k<<<NBLK, 1024>>>();
    scanB_k<<<1, 32>>>();
    scanC_k<<<(NSLOT + 255) / 256, 256>>>();
    fill_k<<<(EE + 255) / 256, 256>>>(eidx, etype);

    // ---- layer 1 ----
    build_h16_k<<<dim3((IN1 + 255) / 256, NN), 256>>>(x, gene_emb);
    aggv_k<<<NSLOT, AGG_T>>>(A1, A1, KP1, SEG1, SEG1 / 8);
    convwT_k<<<dim3(KP1 / 32, (OUT1 + 31) / 32), dim3(32, 8)>>>(root1, W1, IN1, SEG1, 5, OUT1, Bh, KP1);
    {
        dim3 grid((OUT1 + 127) / 128, (NN + 255) / 256);
        hgemm_k<<<grid, GT, DSMEM>>>(A1, Bh, b1, nullptr, 0, A2, KP2, NN, OUT1, KP1, 1);
    }

    // ---- layer 2 ----
    aggv_k<<<NSLOT, AGG_T>>>(A2, A2, KP2, SEG2, SEG2 / 8);
    convwT_k<<<dim3(KP2 / 32, (OUT2 + 31) / 32), dim3(32, 8)>>>(root2, W2, OUT1, SEG2, 5, OUT2, Bh, KP2);
    {
        dim3 grid((OUT2 + 127) / 128, (NN + 255) / 256);
        hgemm_k<<<grid, GT, DSMEM>>>(A2, Bh, b2, nullptr, 0, A3, KP3, NN, OUT2, KP2, 1);
    }

    // ---- MLP lin1 ----
    convwT_k<<<dim3(KP3 / 32, (OUT3 + 31) / 32), dim3(32, 8)>>>(lin1_w, nullptr, OUT2, KP3, 1, OUT3, Bh, KP3);
    {
        dim3 grid((OUT3 + 127) / 128, (NN + 255) / 256);
        hgemm_k<<<grid, GT, DSMEM>>>(A3, Bh, lin1_b, H3, OUT3, nullptr, 0, NN, OUT3, KP3, 1);
    }

    // ---- lin2 + log_softmax ----
    head_k<<<(NN + 7) / 8, 256>>>(lin2_w, lin2_b, out);
}

// round 17
// speedup vs baseline: 1.0023x; 1.0023x over previous
#include <cuda_runtime.h>
#include <cuda_fp16.h>
#include <cstdint>
#include <cstddef>

// ---------------- problem constants ----------------
#define N_X    20000
#define N_GENE 4264
#define NN     24264
#define EE     120000
#define NREL   4
#define NSLOT  (NREL * NN)
#define NBLK   ((NSLOT + 1023) / 1024)

#define IN1    1613
#define OUT1   1600
#define OUT2   900
#define OUT3   400

// segmented fp16 layouts (16B-aligned segments)
#define SEG1   1616      // layer1 segment width (1613 valid + 3 zero)
#define KP1    8096      // 5*1616=8080, padded to mult of 32
#define SEG2   1600
#define KP2    8000      // 5*1600
#define KP3    960       // 900 padded

// ---------------- device scratch ----------------
__device__ __half gA1[(size_t)NN * KP1 + 64];
__device__ __half gA2[(size_t)NN * KP2 + 64];
__device__ __half gA3[(size_t)NN * KP3 + 64];
__device__ __half gBh[(size_t)OUT1 * KP1 + 64];
__device__ __half gB2[(size_t)OUT2 * KP2 + 64];
__device__ __half gB3[(size_t)OUT3 * KP3 + 64];
__device__ float  gH3[(size_t)NN * OUT3 + 64];
__device__ int    gCntI[NSLOT];
__device__ int    gOff[NSLOT + 1];
__device__ int    gCur[NSLOT];
__device__ int    gBlkSum[NBLK];
__device__ int    gSrcSorted[EE];
__device__ int    g_is64;

// ---------------- edge dtype detect ----------------
__global__ void detect_k(const unsigned int* __restrict__ ei) {
    if (blockIdx.x == 0 && threadIdx.x == 0) {
        int is64 = 1;
        for (int i = 1; i < 256; i += 2)
            if (ei[i] != 0u) { is64 = 0; break; }
        g_is64 = is64;
    }
}
__device__ __forceinline__ int read_idx(const void* p, int i, int is64) {
    return is64 ? (int)((const long long*)p)[i] : ((const int*)p)[i];
}

// ---------------- counting sort of edges by (rel,dst) ----------------
__global__ void zero_i_k(int* __restrict__ p, int n) {
    int i = blockIdx.x * blockDim.x + threadIdx.x;
    if (i < n) p[i] = 0;
}
__global__ void count_i_k(const void* __restrict__ ei, const void* __restrict__ et) {
    int e = blockIdx.x * blockDim.x + threadIdx.x;
    if (e >= EE) return;
    int is64 = g_is64;
    int r   = read_idx(et, e, is64);
    int dst = read_idx(ei, EE + e, is64);
    atomicAdd(&gCntI[r * NN + dst], 1);
}
__global__ void scanA_k() {
    __shared__ int sdata[1024];
    const int tid = threadIdx.x;
    const int i = blockIdx.x * 1024 + tid;
    int v = (i < NSLOT) ? gCntI[i] : 0;
    sdata[tid] = v;
    __syncthreads();
    for (int off = 1; off < 1024; off <<= 1) {
        int t = (tid >= off) ? sdata[tid - off] : 0;
        __syncthreads();
        sdata[tid] += t;
        __syncthreads();
    }
    if (i < NSLOT) gOff[i] = sdata[tid] - v;
    if (tid == 1023) gBlkSum[blockIdx.x] = sdata[1023];
}
__global__ void scanB_k() {
    if (threadIdx.x == 0) {
        int acc = 0;
        for (int b = 0; b < NBLK; b++) {
            int v = gBlkSum[b];
            gBlkSum[b] = acc;
            acc += v;
        }
    }
}
__global__ void scanC_k() {
    int i = blockIdx.x * blockDim.x + threadIdx.x;
    if (i < NSLOT) {
        int v = gOff[i] + gBlkSum[i >> 10];
        gOff[i] = v;
        gCur[i] = v;
    }
    if (i == 0) gOff[NSLOT] = EE;
}
__global__ void fill_k(const void* __restrict__ ei, const void* __restrict__ et) {
    int e = blockIdx.x * blockDim.x + threadIdx.x;
    if (e >= EE) return;
    int is64 = g_is64;
    int src = read_idx(ei, e, is64);
    int dst = read_idx(ei, EE + e, is64);
    int r   = read_idx(et, e, is64);
    int p = atomicAdd(&gCur[r * NN + dst], 1);
    gSrcSorted[p] = src;
}

// ---------------- build h (fp16) ----------------
__global__ void build_h16_k(const float* __restrict__ x, const float* __restrict__ ge) {
    int i = blockIdx.y;
    int k = blockIdx.x * blockDim.x + threadIdx.x;
    if (k >= IN1) return;
    float v = (i < N_X) ? x[(size_t)i * IN1 + k] : ge[(size_t)(i - N_X) * IN1 + k];
    gA1[(size_t)i * KP1 + k] = __float2half(v);
}

// ---------------- vectorized gather aggregation (uint4, atomic-free) ----------------
#define AGG_T 128
__global__ __launch_bounds__(AGG_T) void aggv_k(
    const __half* __restrict__ src, __half* __restrict__ dstA,
    int ld, int segH, int nvec)
{
    const int slot = blockIdx.x;
    const int r    = slot / NN;
    const int drow = slot - r * NN;
    const int beg = gOff[slot];
    const int end = gOff[slot + 1];
    const int tid = threadIdx.x;
    uint4* outv = (uint4*)(dstA + (size_t)drow * ld + (size_t)(r + 1) * segH);

    const int v0 = tid, v1 = tid + AGG_T;
    if (end <= beg) {
        uint4 z = make_uint4(0, 0, 0, 0);
        if (v0 < nvec) outv[v0] = z;
        if (v1 < nvec) outv[v1] = z;
        return;
    }
    const float inv = 1.0f / (float)(end - beg);
    float a0[8], a1[8];
#pragma unroll
    for (int j = 0; j < 8; j++) { a0[j] = 0.f; a1[j] = 0.f; }

    for (int e = beg; e < end; e++) {
        const uint4* s = (const uint4*)(src + (size_t)gSrcSorted[e] * ld);
        if (v0 < nvec) {
            uint4 q = s[v0];
            float2 f0 = __half22float2(*(__half2*)&q.x);
            float2 f1 = __half22float2(*(__half2*)&q.y);
            float2 f2 = __half22float2(*(__half2*)&q.z);
            float2 f3 = __half22float2(*(__half2*)&q.w);
            a0[0] += f0.x; a0[1] += f0.y; a0[2] += f1.x; a0[3] += f1.y;
            a0[4] += f2.x; a0[5] += f2.y; a0[6] += f3.x; a0[7] += f3.y;
        }
        if (v1 < nvec) {
            uint4 q = s[v1];
            float2 f0 = __half22float2(*(__half2*)&q.x);
            float2 f1 = __half22float2(*(__half2*)&q.y);
            float2 f2 = __half22float2(*(__half2*)&q.z);
            float2 f3 = __half22float2(*(__half2*)&q.w);
            a1[0] += f0.x; a1[1] += f0.y; a1[2] += f1.x; a1[3] += f1.y;
            a1[4] += f2.x; a1[5] += f2.y; a1[6] += f3.x; a1[7] += f3.y;
        }
    }
    if (v0 < nvec) {
        uint4 q;
        *(__half2*)&q.x = __floats2half2_rn(a0[0] * inv, a0[1] * inv);
        *(__half2*)&q.y = __floats2half2_rn(a0[2] * inv, a0[3] * inv);
        *(__half2*)&q.z = __floats2half2_rn(a0[4] * inv, a0[5] * inv);
        *(__half2*)&q.w = __floats2half2_rn(a0[6] * inv, a0[7] * inv);
        outv[v0] = q;
    }
    if (v1 < nvec) {
        uint4 q;
        *(__half2*)&q.x = __floats2half2_rn(a1[0] * inv, a1[1] * inv);
        *(__half2*)&q.y = __floats2half2_rn(a1[2] * inv, a1[3] * inv);
        *(__half2*)&q.z = __floats2half2_rn(a1[4] * inv, a1[5] * inv);
        *(__half2*)&q.w = __floats2half2_rn(a1[6] * inv, a1[7] * inv);
        outv[v1] = q;
    }
}

// ---------------- coalesced segmented weight transpose -> fp16 K-major ----------------
__global__ void convwT_k(const float* __restrict__ root, const float* __restrict__ W,
                         int rows1, int segW, int nseg,
                         int Nout, __half* __restrict__ D, int ldd) {
    __shared__ float tile[32][33];
    const int k0 = blockIdx.x * 32;
    const int n0 = blockIdx.y * 32;
    const int tx = threadIdx.x, ty = threadIdx.y;   // 32 x 8
#pragma unroll
    for (int j = 0; j < 32; j += 8) {
        int k = k0 + ty + j;
        int n = n0 + tx;
        float v = 0.f;
        if (n < Nout && k < ldd) {
            int seg = k / segW;
            int idx = k - seg * segW;
            if (seg < nseg && idx < rows1) {
                if (seg == 0) v = root[(size_t)idx * Nout + n];
                else          v = W[(size_t)((seg - 1) * rows1 + idx) * Nout + n];
            }
        }
        tile[ty + j][tx] = v;
    }
    __syncthreads();
#pragma unroll
    for (int j = 0; j < 32; j += 8) {
        int n = n0 + ty + j;
        int k = k0 + tx;
        if (n < Nout && k < ldd)
            D[(size_t)n * ldd + k] = __float2half(tile[tx][ty + j]);
    }
}

// ---------------- mma.sync fp16 GEMM (unchanged known-good core) ----------------
#define GT      256
#define ROW_B   80
#define A_TILE  (256 * ROW_B)
#define B_TILE  (128 * ROW_B)
#define OFF_A   0
#define OFF_B   A_TILE
#define STAGE_B (A_TILE + B_TILE)
#define NSTAGE  4
#define DSMEM   (NSTAGE * STAGE_B)

__device__ __forceinline__ void cp_async16(uint32_t dst, const void* src, bool ok) {
    int sz = ok ? 16 : 0;
    asm volatile("cp.async.cg.shared.global [%0], [%1], 16, %2;"
                 :: "r"(dst), "l"(src), "r"(sz));
}
__device__ __forceinline__ uint32_t smem_u32(const void* p) {
    uint32_t a;
    asm("{ .reg .u64 t; cvta.to.shared.u64 t, %1; cvt.u32.u64 %0, t; }" : "=r"(a) : "l"(p));
    return a;
}
__device__ __forceinline__ void ldsm4(uint32_t* r, uint32_t addr) {
    asm volatile("ldmatrix.sync.aligned.m8n8.x4.shared.b16 {%0,%1,%2,%3}, [%4];"
                 : "=r"(r[0]), "=r"(r[1]), "=r"(r[2]), "=r"(r[3]) : "r"(addr));
}
__device__ __forceinline__ void mma_f16(float* d, const uint32_t* a, uint32_t b0, uint32_t b1) {
    asm volatile("mma.sync.aligned.m16n8k16.row.col.f32.f16.f16.f32 "
                 "{%0,%1,%2,%3}, {%4,%5,%6,%7}, {%8,%9}, {%0,%1,%2,%3};"
                 : "+f"(d[0]), "+f"(d[1]), "+f"(d[2]), "+f"(d[3])
                 : "r"(a[0]), "r"(a[1]), "r"(a[2]), "r"(a[3]), "r"(b0), "r"(b1));
}

__global__ __launch_bounds__(GT, 1) void hgemm_k(
    const __half* __restrict__ Ah, const __half* __restrict__ Bh,
    const float* __restrict__ bias,
    float* __restrict__ C32, int ldc32,
    __half* __restrict__ C16, int ldc16,
    int M, int Ncols, int Kpad, int doRelu)
{
    extern __shared__ char dsm[];
    const uint32_t dsmU = smem_u32(dsm);

    const int tid  = threadIdx.x;
    const int wid  = tid >> 5;
    const int lane = tid & 31;
    const int warp_m = wid & 3;
    const int warp_n = wid >> 2;
    const int mbase = blockIdx.y * 256;
    const int nbase = blockIdx.x * 128;
    const int nChunks = Kpad >> 5;

    float cf[4][8][4];
#pragma unroll
    for (int mi = 0; mi < 4; mi++)
#pragma unroll
        for (int nb = 0; nb < 8; nb++)
#pragma unroll
            for (int r = 0; r < 4; r++) cf[mi][nb][r] = 0.f;

    const bool mOK = (mbase + tid) < M;
    const int  bRow = tid >> 1;
    const int  bHalf = tid & 1;
    const bool nOK = (nbase + bRow) < Ncols;
    const __half* pA = Ah + (size_t)(mbase + tid) * Kpad;
    const __half* pB = Bh + (size_t)(nbase + bRow) * Kpad + bHalf * 16;
    const uint32_t dstA = OFF_A + tid * ROW_B;
    const uint32_t dstB = OFF_B + bRow * ROW_B + bHalf * 32;

    auto issue = [&](int i) {
        const int s = i & 3;
        const int k0 = i << 5;
        const uint32_t st = dsmU + s * STAGE_B;
#pragma unroll
        for (int c = 0; c < 4; c++)
            cp_async16(st + dstA + c * 16, pA + k0 + c * 8, mOK);
#pragma unroll
        for (int c = 0; c < 2; c++)
            cp_async16(st + dstB + c * 16, pB + k0 + c * 8, nOK);
        asm volatile("cp.async.commit_group;" ::: "memory");
    };

    issue(0);
    if (nChunks > 1) issue(1);
    if (nChunks > 2) issue(2);

    const int lrow  = lane & 15;
    const int lhalf = (lane >> 4) << 4;
    const uint32_t aOff = OFF_A + (warp_m * 64 + lrow) * ROW_B + lhalf;
    const uint32_t bOff = OFF_B + (warp_n * 64 + lrow) * ROW_B + lhalf;

    for (int i = 0; i < nChunks; i++) {
        const int rem = nChunks - 1 - i;
        if (rem >= 2)      asm volatile("cp.async.wait_group 2;" ::: "memory");
        else if (rem == 1) asm volatile("cp.async.wait_group 1;" ::: "memory");
        else               asm volatile("cp.async.wait_group 0;" ::: "memory");
        __syncthreads();
        if (i + 3 < nChunks) issue(i + 3);

        const uint32_t st = dsmU + (i & 3) * STAGE_B;
        const uint32_t aA = st + aOff;
        const uint32_t bA = st + bOff;

#pragma unroll
        for (int kk = 0; kk < 2; kk++) {
            const uint32_t kByte = kk << 5;
            uint32_t aQ[4][4], bQ[4][4];
#pragma unroll
            for (int mi = 0; mi < 4; mi++)
                ldsm4(aQ[mi], aA + mi * (16 * ROW_B) + kByte);
#pragma unroll
            for (int nj = 0; nj < 4; nj++)
                ldsm4(bQ[nj], bA + nj * (16 * ROW_B) + kByte);
#pragma unroll
            for (int mi = 0; mi < 4; mi++)
#pragma unroll
                for (int nj = 0; nj < 4; nj++) {
                    mma_f16(cf[mi][nj * 2 + 0], aQ[mi], bQ[nj][0], bQ[nj][2]);
                    mma_f16(cf[mi][nj * 2 + 1], aQ[mi], bQ[nj][1], bQ[nj][3]);
                }
        }
    }

    const int r0 = mbase + warp_m * 64 + (lane >> 2);
    const int c0 = nbase + warp_n * 64 + ((lane & 3) << 1);
#pragma unroll
    for (int nb = 0; nb < 8; nb++) {
        const int gc = c0 + nb * 8;
        if (gc >= Ncols) continue;
        const float bv0 = bias[gc], bv1 = bias[gc + 1];
#pragma unroll
        for (int mi = 0; mi < 4; mi++) {
            int gr = r0 + mi * 16;
            float v0 = cf[mi][nb][0] + bv0, v1 = cf[mi][nb][1] + bv1;
            float v2 = cf[mi][nb][2] + bv0, v3 = cf[mi][nb][3] + bv1;
            if (doRelu) {
                v0 = fmaxf(v0, 0.f); v1 = fmaxf(v1, 0.f);
                v2 = fmaxf(v2, 0.f); v3 = fmaxf(v3, 0.f);
            }
            if (C32) {
                if (gr < M)     *(float2*)(C32 + (size_t)gr * ldc32 + gc)       = make_float2(v0, v1);
                if (gr + 8 < M) *(float2*)(C32 + (size_t)(gr + 8) * ldc32 + gc) = make_float2(v2, v3);
            }
            if (C16) {
                if (gr < M)     *(__half2*)(C16 + (size_t)gr * ldc16 + gc)       = __floats2half2_rn(v0, v1);
                if (gr + 8 < M) *(__half2*)(C16 + (size_t)(gr + 8) * ldc16 + gc) = __floats2half2_rn(v2, v3);
            }
        }
    }
}

// ---------------- final head ----------------
__global__ void head_k(const float* __restrict__ lin2, const float* __restrict__ b,
                       float* __restrict__ out) {
    int row  = blockIdx.x * (blockDim.x >> 5) + (threadIdx.x >> 5);
    int lane = threadIdx.x & 31;
    if (row >= NN) return;
    const float* h = gH3 + (size_t)row * OUT3;
    float a0 = 0.f, a1 = 0.f;
    for (int k = lane; k < OUT3; k += 32) {
        float v = h[k];
        a0 += v * lin2[k * 2 + 0];
        a1 += v * lin2[k * 2 + 1];
    }
#pragma unroll
    for (int o = 16; o; o >>= 1) {
        a0 += __shfl_down_sync(0xffffffffu, a0, o);
        a1 += __shfl_down_sync(0xffffffffu, a1, o);
    }
    if (lane == 0) {
        a0 += b[0]; a1 += b[1];
        float m = fmaxf(a0, a1);
        float lse = m + logf(expf(a0 - m) + expf(a1 - m));
        out[row * 2 + 0] = a0 - lse;
        out[row * 2 + 1] = a1 - lse;
    }
}

// ---------------- host ----------------
static float* sym_addr_f(const void* s) { void* p = nullptr; cudaGetSymbolAddress(&p, s); return (float*)p; }
static __half* sym_addr_h(const void* s) { void* p = nullptr; cudaGetSymbolAddress(&p, s); return (__half*)p; }
static int* sym_addr_i(const void* s) { void* p = nullptr; cudaGetSymbolAddress(&p, s); return (int*)p; }

extern "C" void kernel_launch(void* const* d_in, const int* in_sizes, int n_in,
                              void* d_out, int out_size) {
    const float* x        = (const float*)d_in[0];
    const void*  eidx     = d_in[1];
    const void*  etype    = d_in[2];
    const float* gene_emb = (const float*)d_in[3];
    const float* W1       = (const float*)d_in[4];
    const float* root1    = (const float*)d_in[5];
    const float* b1       = (const float*)d_in[6];
    const float* W2       = (const float*)d_in[7];
    const float* root2    = (const float*)d_in[8];
    const float* b2       = (const float*)d_in[9];
    const float* lin1_w   = (const float*)d_in[10];
    const float* lin1_b   = (const float*)d_in[11];
    const float* lin2_w   = (const float*)d_in[12];
    const float* lin2_b   = (const float*)d_in[13];
    float* out = (float*)d_out;

    __half* A1 = sym_addr_h(gA1);
    __half* A2 = sym_addr_h(gA2);
    __half* A3 = sym_addr_h(gA3);
    __half* B1 = sym_addr_h(gBh);
    __half* B2 = sym_addr_h(gB2);
    __half* B3 = sym_addr_h(gB3);
    float*  H3 = sym_addr_f(gH3);
    int*    CntI = sym_addr_i(gCntI);

    // one-time setup (first call is the non-captured correctness run)
    static bool init_done = false;
    static cudaStream_t sS;
    static cudaEvent_t evFork, evBH, evC1, evC23;
    if (!init_done) {
        cudaFuncSetAttribute(hgemm_k, cudaFuncAttributeMaxDynamicSharedMemorySize, DSMEM);
        cudaStreamCreateWithFlags(&sS, cudaStreamNonBlocking);
        cudaEventCreateWithFlags(&evFork, cudaEventDisableTiming);
        cudaEventCreateWithFlags(&evBH,   cudaEventDisableTiming);
        cudaEventCreateWithFlags(&evC1,   cudaEventDisableTiming);
        cudaEventCreateWithFlags(&evC23,  cudaEventDisableTiming);
        init_done = true;
    }

    // ---- fork side stream ----
    cudaEventRecord(evFork, 0);
    cudaStreamWaitEvent(sS, evFork, 0);

    // side stream: build_h + all weight transposes (independent of edges/GEMMs)
    build_h16_k<<<dim3((IN1 + 255) / 256, NN), 256, 0, sS>>>(x, gene_emb);
    cudaEventRecord(evBH, sS);
    convwT_k<<<dim3(KP1 / 32, (OUT1 + 31) / 32), dim3(32, 8), 0, sS>>>(
        root1, W1, IN1, SEG1, 5, OUT1, B1, KP1);
    cudaEventRecord(evC1, sS);
    convwT_k<<<dim3(KP2 / 32, (OUT2 + 31) / 32), dim3(32, 8), 0, sS>>>(
        root2, W2, OUT1, SEG2, 5, OUT2, B2, KP2);
    convwT_k<<<dim3(KP3 / 32, (OUT3 + 31) / 32), dim3(32, 8), 0, sS>>>(
        lin1_w, nullptr, OUT2, KP3, 1, OUT3, B3, KP3);
    cudaEventRecord(evC23, sS);

    // main stream: edge preprocessing (counting sort by (rel,dst))
    detect_k<<<1, 1>>>((const unsigned int*)eidx);
    zero_i_k<<<(NSLOT + 255) / 256, 256>>>(CntI, NSLOT);
    count_i_k<<<(EE + 255) / 256, 256>>>(eidx, etype);
    scanA_k<<<NBLK, 1024>>>();
    scanB_k<<<1, 32>>>();
    scanC_k<<<(NSLOT + 255) / 256, 256>>>();
    fill_k<<<(EE + 255) / 256, 256>>>(eidx, etype);

    // ---- layer 1 ----
    cudaStreamWaitEvent(0, evBH, 0);          // aggv_1 needs build_h
    aggv_k<<<NSLOT, AGG_T>>>(A1, A1, KP1, SEG1, SEG1 / 8);
    cudaStreamWaitEvent(0, evC1, 0);          // GEMM1 needs B1
    {
        dim3 grid((OUT1 + 127) / 128, (NN + 255) / 256);
        hgemm_k<<<grid, GT, DSMEM>>>(A1, B1, b1, nullptr, 0, A2, KP2, NN, OUT1, KP1, 1);
    }

    // ---- layer 2 ----
    aggv_k<<<NSLOT, AGG_T>>>(A2, A2, KP2, SEG2, SEG2 / 8);
    cudaStreamWaitEvent(0, evC23, 0);         // GEMM2/3 need B2/B3
    {
        dim3 grid((OUT2 + 127) / 128, (NN + 255) / 256);
        hgemm_k<<<grid, GT, DSMEM>>>(A2, B2, b2, nullptr, 0, A3, KP3, NN, OUT2, KP2, 1);
    }

    // ---- MLP lin1 ----
    {
        dim3 grid((OUT3 + 127) / 128, (NN + 255) / 256);
        hgemm_k<<<grid, GT, DSMEM>>>(A3, B3, lin1_b, H3, OUT3, nullptr, 0, NN, OUT3, KP3, 1);
    }

    // ---- lin2 + log_softmax ----
    head_k<<<(NN + 7) / 8, 256>>>(lin2_w, lin2_b, out);
}